// round 15
// baseline (speedup 1.0000x reference)
#include <cuda_runtime.h>
#include <cuda_bf16.h>
#include <math.h>
#include <stdint.h>

// Problem constants
#define BATCH 16
#define SEQ   512
#define DMODEL 2048
#define NHEADS 16
#define NGROUPS 4
#define HEADD 128
#define PPG   (NHEADS / NGROUPS)   // 4
#define KVD   (NGROUPS * HEADD)    // 512
#define QKVROW 3072                // fused Q|K|V row width
#define KOFF  2048                 // K column offset in qkv row
#define VOFF  2560                 // V column offset in qkv row
#define MROWS (BATCH * SEQ)        // 8192

#define INV_SQRT_HD 0.08838834764831845f
#define LN10000 9.210340371976184f

// ---------------------------------------------------------------------------
// Scratch buffers
// ---------------------------------------------------------------------------
__device__ float g_qkv[(size_t)MROWS * QKVROW];    // 96 MB  (Q | K | V per row)
__device__ float g_attn[(size_t)MROWS * DMODEL];   // 64 MB (tf32-rounded)
__device__ float g_wqkvt[(size_t)QKVROW * DMODEL]; // 24 MB  [WqT ; WkT ; WvT]
__device__ float g_wot[(size_t)DMODEL * DMODEL];   // 16 MB
__device__ float g_bqkv[QKVROW];
__device__ float g_sintab[SEQ * 64];
__device__ float g_costab[SEQ * 64];

// ---------------------------------------------------------------------------
// helpers
// ---------------------------------------------------------------------------
__device__ __forceinline__ unsigned f2tf32(float x) {
    unsigned r;
    asm("cvt.rna.tf32.f32 %0, %1;" : "=r"(r) : "f"(x));
    return r;
}
__device__ __forceinline__ float rna_tf32f(float x) { return __uint_as_float(f2tf32(x)); }
__device__ __forceinline__ uint32_t cvt_frag(uint32_t bits) {
    return f2tf32(__uint_as_float(bits));
}

__device__ __forceinline__ uint32_t smem_u32(const void* p) {
    uint32_t a;
    asm("{ .reg .u64 t; cvta.to.shared.u64 t, %1; cvt.u32.u64 %0, t; }" : "=r"(a) : "l"(p));
    return a;
}
__device__ __forceinline__ void cp16(uint32_t saddr, const void* g) {
    asm volatile("cp.async.cg.shared.global [%0], [%1], 16;" :: "r"(saddr), "l"(g));
}
__device__ __forceinline__ void cp_commit() { asm volatile("cp.async.commit_group;" ::: "memory"); }

__device__ __forceinline__ void ldsm_x4(uint32_t a[4], uint32_t addr) {
    asm volatile("ldmatrix.sync.aligned.m8n8.x4.shared.b16 {%0,%1,%2,%3}, [%4];"
                 : "=r"(a[0]), "=r"(a[1]), "=r"(a[2]), "=r"(a[3]) : "r"(addr));
}

__device__ __forceinline__ void mma_tf32(float c[4], const uint32_t a[4], const uint32_t b[2]) {
    asm volatile(
        "mma.sync.aligned.m16n8k8.row.col.f32.tf32.tf32.f32 "
        "{%0,%1,%2,%3}, {%4,%5,%6,%7}, {%8,%9}, {%0,%1,%2,%3};"
        : "+f"(c[0]), "+f"(c[1]), "+f"(c[2]), "+f"(c[3])
        : "r"(a[0]), "r"(a[1]), "r"(a[2]), "r"(a[3]), "r"(b[0]), "r"(b[1]));
}

// ---------------------------------------------------------------------------
// Pre-pass kernels
// ---------------------------------------------------------------------------
__global__ void rope_table_kernel(float* __restrict__ sintab, float* __restrict__ costab) {
    const int s = blockIdx.x;
    const int i = threadIdx.x;   // 0..63
    float inv_freq = expf((float)i * (-LN10000 / 64.0f));
    float sn, cs;
    sincosf((float)s * inv_freq, &sn, &cs);
    sintab[s * 64 + i] = sn;
    costab[s * 64 + i] = cs;
}

__global__ void transpose_round_kernel(const float* __restrict__ W, float* __restrict__ WT,
                                       int K, int N) {
    __shared__ float t[32][33];
    int n0 = blockIdx.x * 32, k0 = blockIdx.y * 32;
    int tx = threadIdx.x, ty = threadIdx.y;
    #pragma unroll
    for (int j = 0; j < 32; j += 8)
        t[ty + j][tx] = W[(size_t)(k0 + ty + j) * N + n0 + tx];
    __syncthreads();
    #pragma unroll
    for (int j = 0; j < 32; j += 8)
        WT[(size_t)(n0 + ty + j) * K + k0 + tx] = rna_tf32f(t[tx][ty + j]);
}

__global__ void concat_bias3_kernel(const float* __restrict__ bq, const float* __restrict__ bk,
                                    const float* __restrict__ bv, float* __restrict__ bqkv) {
    int i = blockIdx.x * blockDim.x + threadIdx.x;
    if (i < QKVROW) {
        float v;
        if (i < KOFF) v = bq[i];
        else if (i < VOFF) v = bk[i - KOFF];
        else v = bv[i - VOFF];
        bqkv[i] = v;
    }
}

// ---------------------------------------------------------------------------
// TF32 mma.sync GEMM: C[M,N] = round(A)[M,K] @ BT[N,K]^T + bias[N]
// A fragments tf32-rounded in-register. Epilogue rounds cols >= roundFrom.
// CTA 128x128, BK=32, 3-stage cp.async, paired-x4 ldmatrix fragments.
// ---------------------------------------------------------------------------
#define BK 32
#define STAGE_BYTES 32768
#define GSM_B_OFF 16384
#define GEMM_SMEM_BYTES (3 * STAGE_BYTES)   // 98304

__device__ __forceinline__ uint32_t swz(int r, int chunk) {
    return (uint32_t)(r * 128 + ((chunk ^ (r & 7)) << 4));
}

__device__ __forceinline__ void gemm_load_stage(const float* __restrict__ A,
                                                const float* __restrict__ BT,
                                                int K, int m0, int n0, int kt,
                                                uint32_t sstage, int tid) {
    const int kbase = kt * BK;
    #pragma unroll
    for (int j = 0; j < 4; j++) {
        int i = tid + j * 256;
        int r = i >> 3, cc = i & 7;
        cp16(sstage + swz(r, cc), A + (size_t)(m0 + r) * K + kbase + cc * 4);
    }
    #pragma unroll
    for (int j = 0; j < 4; j++) {
        int i = tid + j * 256;
        int r = i >> 3, cc = i & 7;
        cp16(sstage + GSM_B_OFF + swz(r, cc), BT + (size_t)(n0 + r) * K + kbase + cc * 4);
    }
}

__global__ __launch_bounds__(256, 2)
void tf32_gemm_pipe(const float* __restrict__ A, const float* __restrict__ BT,
                    const float* __restrict__ bias, float* __restrict__ C,
                    int M, int N, int K, int roundFrom) {
    extern __shared__ char smem[];
    const uint32_t sbase = smem_u32(smem);
    const int tid = threadIdx.x;
    const int lane = tid & 31;
    const int wid = tid >> 5;
    const int warpRow = (wid >> 2) * 64;
    const int warpCol = (wid & 3) * 32;
    const int m0 = blockIdx.y * 128;
    const int n0 = blockIdx.x * 128;

    float acc[4][4][4];
    #pragma unroll
    for (int i = 0; i < 4; i++)
        #pragma unroll
        for (int j = 0; j < 4; j++)
            #pragma unroll
            for (int r = 0; r < 4; r++) acc[i][j][r] = 0.0f;

    const int NT = K / BK;

    const int a_sub = lane >> 3;
    const int a_row_in = (lane & 7) + (a_sub & 1) * 8;
    const int a_chunk_add = a_sub >> 1;
    const int b_sub = (lane >> 3) & 1;
    const int b_pair_row = ((lane >> 4) & 1) * 8 + (lane & 7);

    gemm_load_stage(A, BT, K, m0, n0, 0, sbase, tid);
    cp_commit();
    gemm_load_stage(A, BT, K, m0, n0, 1, sbase + STAGE_BYTES, tid);
    cp_commit();

    for (int kt = 0; kt < NT; kt++) {
        if (kt + 2 < NT) {
            asm volatile("cp.async.wait_group 1;" ::: "memory");
        } else {
            asm volatile("cp.async.wait_group 0;" ::: "memory");
        }
        __syncthreads();
        if (kt + 2 < NT) {
            gemm_load_stage(A, BT, K, m0, n0, kt + 2,
                            sbase + ((kt + 2) % 3) * STAGE_BYTES, tid);
            cp_commit();
        }

        const uint32_t sA = sbase + (kt % 3) * STAGE_BYTES;
        const uint32_t sB = sA + GSM_B_OFF;

        #pragma unroll
        for (int ks = 0; ks < 4; ks++) {
            uint32_t af[4][4];
            uint32_t bf[2][4];
            #pragma unroll
            for (int it = 0; it < 4; it++) {
                int r = warpRow + it * 16 + a_row_in;
                ldsm_x4(af[it], sA + swz(r, ks * 2 + a_chunk_add));
                af[it][0] = cvt_frag(af[it][0]);
                af[it][1] = cvt_frag(af[it][1]);
                af[it][2] = cvt_frag(af[it][2]);
                af[it][3] = cvt_frag(af[it][3]);
            }
            #pragma unroll
            for (int jp = 0; jp < 2; jp++) {
                int r = warpCol + jp * 16 + b_pair_row;
                ldsm_x4(bf[jp], sB + swz(r, ks * 2 + b_sub));
            }
            #pragma unroll
            for (int it = 0; it < 4; it++) {
                #pragma unroll
                for (int jp = 0; jp < 2; jp++) {
                    mma_tf32(acc[it][jp * 2 + 0], af[it], &bf[jp][0]);
                    mma_tf32(acc[it][jp * 2 + 1], af[it], &bf[jp][2]);
                }
            }
        }
    }

    const int lr = lane >> 2;
    const int lc = lane & 3;
    #pragma unroll
    for (int it = 0; it < 4; it++) {
        #pragma unroll
        for (int jt = 0; jt < 4; jt++) {
            int row = m0 + warpRow + it * 16 + lr;
            int col = n0 + warpCol + jt * 8 + 2 * lc;
            float b0 = bias[col];
            float b1 = bias[col + 1];
            float2 v0 = make_float2(acc[it][jt][0] + b0, acc[it][jt][1] + b1);
            float2 v1 = make_float2(acc[it][jt][2] + b0, acc[it][jt][3] + b1);
            if (col >= roundFrom) {
                v0.x = rna_tf32f(v0.x); v0.y = rna_tf32f(v0.y);
                v1.x = rna_tf32f(v1.x); v1.y = rna_tf32f(v1.y);
            }
            *reinterpret_cast<float2*>(&C[(size_t)row * N + col]) = v0;
            *reinterpret_cast<float2*>(&C[(size_t)(row + 8) * N + col]) = v1;
        }
    }
}

// ---------------------------------------------------------------------------
// fast fused RMSNorm + RoPE: one warp per 128-vector, table-based trig.
// ---------------------------------------------------------------------------
__global__ __launch_bounds__(256)
void rmsnorm_rope_fast(float* __restrict__ buf, const float* __restrict__ scale,
                       const float* __restrict__ sintab, const float* __restrict__ costab,
                       int heads_per_row, int rowstride, float post_scale) {
    const int vec = blockIdx.x * 8 + (threadIdx.x >> 5);
    const int lane = threadIdx.x & 31;
    const int row = vec / heads_per_row;
    const int head = vec % heads_per_row;
    float* ptr = buf + (size_t)row * rowstride + head * HEADD + lane * 4;
    const int s = row & (SEQ - 1);

    float4 v = *reinterpret_cast<const float4*>(ptr);
    float sq = fmaf(v.x, v.x, fmaf(v.y, v.y, fmaf(v.z, v.z, v.w * v.w)));
    #pragma unroll
    for (int o = 16; o > 0; o >>= 1) sq += __shfl_xor_sync(0xffffffffu, sq, o);
    const float r = rsqrtf(sq * (1.0f / 128.0f) + 1e-6f);

    const float4 sc = *reinterpret_cast<const float4*>(scale + lane * 4);
    const float a0 = v.x * r * sc.x;
    const float a1 = v.y * r * sc.y;
    const float a2 = v.z * r * sc.z;
    const float a3 = v.w * r * sc.w;

    const float2 sn = *reinterpret_cast<const float2*>(sintab + s * 64 + lane * 2);
    const float2 cs = *reinterpret_cast<const float2*>(costab + s * 64 + lane * 2);

    float4 o4;
    o4.x = rna_tf32f(fmaf(a0, cs.x, -a1 * sn.x) * post_scale);
    o4.y = rna_tf32f(fmaf(a0, sn.x,  a1 * cs.x) * post_scale);
    o4.z = rna_tf32f(fmaf(a2, cs.y, -a3 * sn.y) * post_scale);
    o4.w = rna_tf32f(fmaf(a2, sn.y,  a3 * cs.y) * post_scale);
    *reinterpret_cast<float4*>(ptr) = o4;
}

// ---------------------------------------------------------------------------
// Tensor-core causal attention over fused qkv rows (stride QKVROW).
// ---------------------------------------------------------------------------
#define ATT_SC_STRIDE 516
#define ATT_Q_OFF  (64 * ATT_SC_STRIDE * 4)            // 132096
#define ATT_KV_OFF (ATT_Q_OFF + 32768)                 // 164864
#define ATT_SMEM_BYTES (ATT_KV_OFF + 65536)            // 230400

__device__ __forceinline__ uint32_t qswz(int r, int c) {
    return (uint32_t)(r * 512 + ((((c ^ r) & 7) | (c & 24)) << 4));
}

__global__ __launch_bounds__(256, 1)
void attention_tc_kernel(const float* __restrict__ QKV, float* __restrict__ O) {
    extern __shared__ char smemraw[];
    float* scores = reinterpret_cast<float*>(smemraw);
    float* Vs = reinterpret_cast<float*>(smemraw + ATT_KV_OFF);
    const uint32_t sbase = smem_u32(smemraw);
    const uint32_t sQ = sbase + ATT_Q_OFF;
    const uint32_t sKV = sbase + ATT_KV_OFF;

    const int tid = threadIdx.x;
    const int lane = tid & 31;
    const int wid = tid >> 5;
    const int qt = blockIdx.x;
    const int bh = blockIdx.y;
    const int b = bh / NHEADS;
    const int h = bh % NHEADS;
    const int g = h / PPG;

    const float* Qbase = QKV + (size_t)b * SEQ * QKVROW + (size_t)h * HEADD;
    const float* Kbase = QKV + (size_t)b * SEQ * QKVROW + KOFF + (size_t)g * HEADD;
    const float* Vbase = QKV + (size_t)b * SEQ * QKVROW + VOFF + (size_t)g * HEADD;

    #pragma unroll
    for (int j = 0; j < 8; j++) {
        int idx = tid + j * 256;
        int r = idx >> 5, c = idx & 31;
        cp16(sQ + qswz(r, c), Qbase + (size_t)(qt * 64 + r) * QKVROW + c * 4);
    }
    #pragma unroll
    for (int j = 0; j < 8; j++) {
        int idx = tid + j * 256;
        int r = idx >> 5, c = idx & 31;
        cp16(sKV + qswz(r, c), Kbase + (size_t)r * QKVROW + c * 4);
    }
    cp_commit();
    asm volatile("cp.async.wait_group 0;" ::: "memory");
    __syncthreads();

    const int a_sub = lane >> 3;
    const int a_row_in = (lane & 7) + (a_sub & 1) * 8;
    const int a_chunk_add = a_sub >> 1;
    const int b_sub = (lane >> 3) & 1;
    const int b_pair_row = ((lane >> 4) & 1) * 8 + (lane & 7);
    const int lr = lane >> 2;
    const int lc = lane & 3;
    const int warpRowS = (wid & 3) * 16;
    const int warpColS = (wid >> 2) * 32;

    // ---------------- phase 1: scores = Q @ K^T ----------------
    for (int kt = 0; kt <= qt; kt++) {
        const int buf = kt & 1;
        if (kt < qt) {
            #pragma unroll
            for (int j = 0; j < 8; j++) {
                int idx = tid + j * 256;
                int r = idx >> 5, c = idx & 31;
                cp16(sKV + (1 - buf) * 32768 + qswz(r, c),
                     Kbase + (size_t)((kt + 1) * 64 + r) * QKVROW + c * 4);
            }
            cp_commit();
        }
        const uint32_t sK = sKV + buf * 32768;

        float acc[4][4];
        #pragma unroll
        for (int i = 0; i < 4; i++)
            #pragma unroll
            for (int j = 0; j < 4; j++) acc[i][j] = 0.0f;

        #pragma unroll
        for (int ks = 0; ks < 16; ks++) {
            uint32_t af[4];
            ldsm_x4(af, sQ + qswz(warpRowS + a_row_in, ks * 2 + a_chunk_add));
            #pragma unroll
            for (int jp = 0; jp < 2; jp++) {
                uint32_t bf[4];
                ldsm_x4(bf, sK + qswz(warpColS + jp * 16 + b_pair_row, ks * 2 + b_sub));
                mma_tf32(acc[jp * 2 + 0], af, &bf[0]);
                mma_tf32(acc[jp * 2 + 1], af, &bf[2]);
            }
        }

        #pragma unroll
        for (int jt = 0; jt < 4; jt++) {
            int r0 = warpRowS + lr;
            int r1 = r0 + 8;
            int c0 = kt * 64 + warpColS + jt * 8 + 2 * lc;
            int g0 = qt * 64 + r0;
            int g1 = qt * 64 + r1;
            float2 v0, v1;
            v0.x = (c0 <= g0) ? acc[jt][0] * INV_SQRT_HD : -1e30f;
            v0.y = (c0 + 1 <= g0) ? acc[jt][1] * INV_SQRT_HD : -1e30f;
            v1.x = (c0 <= g1) ? acc[jt][2] * INV_SQRT_HD : -1e30f;
            v1.y = (c0 + 1 <= g1) ? acc[jt][3] * INV_SQRT_HD : -1e30f;
            *reinterpret_cast<float2*>(&scores[r0 * ATT_SC_STRIDE + c0]) = v0;
            *reinterpret_cast<float2*>(&scores[r1 * ATT_SC_STRIDE + c0]) = v1;
        }
        if (kt < qt) asm volatile("cp.async.wait_group 0;" ::: "memory");
        __syncthreads();
    }

    // prefetch V tile 0
    #pragma unroll
    for (int j = 0; j < 8; j++) {
        int idx = tid + j * 256;
        int r = idx >> 5, c = idx & 31;
        cp16(sKV + r * 528 + c * 16, Vbase + (size_t)r * QKVROW + c * 4);
    }
    cp_commit();

    // ---------------- phase 2: softmax ----------------
    {
        const int ncols = (qt + 1) * 64;
        for (int r = wid; r < 64; r += 8) {
            float* row = &scores[r * ATT_SC_STRIDE];
            float m = -1e30f;
            for (int c = lane; c < ncols; c += 32) m = fmaxf(m, row[c]);
            #pragma unroll
            for (int o = 16; o > 0; o >>= 1) m = fmaxf(m, __shfl_xor_sync(0xffffffffu, m, o));
            float sum = 0.0f;
            for (int c = lane; c < ncols; c += 32) {
                float e = __expf(row[c] - m);
                row[c] = e;
                sum += e;
            }
            #pragma unroll
            for (int o = 16; o > 0; o >>= 1) sum += __shfl_xor_sync(0xffffffffu, sum, o);
            float inv = 1.0f / sum;
            for (int c = lane; c < ncols; c += 32) row[c] = rna_tf32f(row[c] * inv);
        }
    }
    __syncthreads();

    // ---------------- phase 3: O = P @ V ----------------
    const int warpRowO = (wid & 3) * 16;
    const int warpColO = (wid >> 2) * 64;
    float oacc[8][4];
    #pragma unroll
    for (int i = 0; i < 8; i++)
        #pragma unroll
        for (int j = 0; j < 4; j++) oacc[i][j] = 0.0f;

    for (int kt = 0; kt <= qt; kt++) {
        asm volatile("cp.async.wait_group 0;" ::: "memory");
        __syncthreads();

        #pragma unroll
        for (int ks = 0; ks < 8; ks++) {
            const int kabs = kt * 64 + ks * 8;
            uint32_t af[4];
            ldsm_x4(af, sbase + (uint32_t)(((warpRowO + a_row_in) * ATT_SC_STRIDE + kabs) * 4)
                        + a_chunk_add * 16);
            #pragma unroll
            for (int jt = 0; jt < 8; jt++) {
                const int ncol = warpColO + jt * 8 + lr;
                uint32_t bf[2];
                bf[0] = __float_as_uint(Vs[(ks * 8 + lc) * 132 + ncol]);
                bf[1] = __float_as_uint(Vs[(ks * 8 + lc + 4) * 132 + ncol]);
                mma_tf32(oacc[jt], af, bf);
            }
        }
        __syncthreads();
        if (kt < qt) {
            #pragma unroll
            for (int j = 0; j < 8; j++) {
                int idx = tid + j * 256;
                int r = idx >> 5, c = idx & 31;
                cp16(sKV + r * 528 + c * 16,
                     Vbase + (size_t)((kt + 1) * 64 + r) * QKVROW + c * 4);
            }
            cp_commit();
        }
    }

    #pragma unroll
    for (int jt = 0; jt < 8; jt++) {
        int r0 = qt * 64 + warpRowO + lr;
        int col = h * HEADD + warpColO + jt * 8 + 2 * lc;
        float* d0 = &O[((size_t)b * SEQ + r0) * DMODEL + col];
        float* d1 = &O[((size_t)b * SEQ + r0 + 8) * DMODEL + col];
        float2 v0 = make_float2(rna_tf32f(oacc[jt][0]), rna_tf32f(oacc[jt][1]));
        float2 v1 = make_float2(rna_tf32f(oacc[jt][2]), rna_tf32f(oacc[jt][3]));
        *reinterpret_cast<float2*>(d0) = v0;
        *reinterpret_cast<float2*>(d1) = v1;
    }
}

// ---------------------------------------------------------------------------
// Launch
// ---------------------------------------------------------------------------
extern "C" void kernel_launch(void* const* d_in, const int* in_sizes, int n_in,
                              void* d_out, int out_size) {
    const float* x  = (const float*)d_in[0];
    const float* Wq = (const float*)d_in[1];
    const float* bq = (const float*)d_in[2];
    const float* Wk = (const float*)d_in[3];
    const float* bk = (const float*)d_in[4];
    const float* Wv = (const float*)d_in[5];
    const float* bv = (const float*)d_in[6];
    const float* Wo = (const float*)d_in[7];
    const float* bo = (const float*)d_in[8];
    const float* qns = (const float*)d_in[9];
    const float* kns = (const float*)d_in[10];
    float* out = (float*)d_out;

    float *qkv, *ab, *wqkvt, *wot, *bqkv, *stab, *ctab;
    cudaGetSymbolAddress((void**)&qkv, g_qkv);
    cudaGetSymbolAddress((void**)&ab, g_attn);
    cudaGetSymbolAddress((void**)&wqkvt, g_wqkvt);
    cudaGetSymbolAddress((void**)&wot, g_wot);
    cudaGetSymbolAddress((void**)&bqkv, g_bqkv);
    cudaGetSymbolAddress((void**)&stab, g_sintab);
    cudaGetSymbolAddress((void**)&ctab, g_costab);

    cudaFuncSetAttribute(tf32_gemm_pipe, cudaFuncAttributeMaxDynamicSharedMemorySize,
                         GEMM_SMEM_BYTES);
    cudaFuncSetAttribute(attention_tc_kernel, cudaFuncAttributeMaxDynamicSharedMemorySize,
                         ATT_SMEM_BYTES);

    cudaStream_t skv;
    cudaEvent_t ev_root, ev_w, ev_gemm, ev_k;
    cudaStreamCreateWithFlags(&skv, cudaStreamNonBlocking);
    cudaEventCreateWithFlags(&ev_root, cudaEventDisableTiming);
    cudaEventCreateWithFlags(&ev_w, cudaEventDisableTiming);
    cudaEventCreateWithFlags(&ev_gemm, cudaEventDisableTiming);
    cudaEventCreateWithFlags(&ev_k, cudaEventDisableTiming);

    dim3 tb(32, 8);

    // fork
    cudaEventRecord(ev_root, 0);
    cudaStreamWaitEvent(skv, ev_root, 0);

    // stream0: rope tables + Wq + Wo transposes
    rope_table_kernel<<<SEQ, 64>>>(stab, ctab);
    transpose_round_kernel<<<dim3(DMODEL / 32, DMODEL / 32), tb>>>(Wq, wqkvt, DMODEL, DMODEL);
    transpose_round_kernel<<<dim3(DMODEL / 32, DMODEL / 32), tb>>>(Wo, wot, DMODEL, DMODEL);

    // skv: Wk/Wv transposes + fused bias
    transpose_round_kernel<<<dim3(KVD / 32, DMODEL / 32), tb, 0, skv>>>(
        Wk, wqkvt + (size_t)KOFF * DMODEL, DMODEL, KVD);
    transpose_round_kernel<<<dim3(KVD / 32, DMODEL / 32), tb, 0, skv>>>(
        Wv, wqkvt + (size_t)VOFF * DMODEL, DMODEL, KVD);
    concat_bias3_kernel<<<12, 256, 0, skv>>>(bq, bk, bv, bqkv);
    cudaEventRecord(ev_w, skv);

    // fused QKV GEMM on stream0 (A = x, rounded in-register); round only V cols
    cudaStreamWaitEvent(0, ev_w, 0);
    tf32_gemm_pipe<<<dim3(QKVROW / 128, MROWS / 128), 256, GEMM_SMEM_BYTES>>>(
        x, wqkvt, bqkv, qkv, MROWS, QKVROW, DMODEL, VOFF);
    cudaEventRecord(ev_gemm, 0);

    // rmsnorm+rope: Q on stream0, K on skv (disjoint columns)
    rmsnorm_rope_fast<<<MROWS * NHEADS / 8, 256>>>(qkv, qns, stab, ctab,
                                                   NHEADS, QKVROW, INV_SQRT_HD);
    cudaStreamWaitEvent(skv, ev_gemm, 0);
    rmsnorm_rope_fast<<<MROWS * NGROUPS / 8, 256, 0, skv>>>(qkv + KOFF, kns, stab, ctab,
                                                            NGROUPS, QKVROW, 1.0f);
    cudaEventRecord(ev_k, skv);

    // join, attention, output projection
    cudaStreamWaitEvent(0, ev_k, 0);
    attention_tc_kernel<<<dim3(SEQ / 64, BATCH * NHEADS), 256, ATT_SMEM_BYTES>>>(qkv, ab);
    tf32_gemm_pipe<<<dim3(DMODEL / 128, MROWS / 128), 256, GEMM_SMEM_BYTES>>>(
        ab, wot, bo, out, MROWS, DMODEL, DMODEL, DMODEL);
}

// round 16
// speedup vs baseline: 1.1458x; 1.1458x over previous
#include <cuda_runtime.h>
#include <cuda_bf16.h>
#include <math.h>
#include <stdint.h>

// Problem constants
#define BATCH 16
#define SEQ   512
#define DMODEL 2048
#define NHEADS 16
#define NGROUPS 4
#define HEADD 128
#define PPG   (NHEADS / NGROUPS)   // 4
#define KVD   (NGROUPS * HEADD)    // 512
#define KVROW 1024                 // fused K|V row width
#define MROWS (BATCH * SEQ)        // 8192

#define INV_SQRT_HD 0.08838834764831845f
#define LN10000 9.210340371976184f

// ---------------------------------------------------------------------------
// Scratch buffers
// ---------------------------------------------------------------------------
__device__ float g_q[(size_t)MROWS * DMODEL];      // 64 MB
__device__ float g_kv[(size_t)MROWS * KVROW];      // 32 MB  (K | V per row)
__device__ float g_attn[(size_t)MROWS * DMODEL];   // 64 MB (tf32-rounded)
__device__ float g_xr[(size_t)MROWS * DMODEL];     // 64 MB (tf32-rounded x)
__device__ float g_wqt[(size_t)DMODEL * DMODEL];   // 16 MB  WqT [N,K]
__device__ float g_wkvt[(size_t)KVROW * DMODEL];   // 8 MB   [WkT ; WvT]
__device__ float g_wot[(size_t)DMODEL * DMODEL];   // 16 MB
__device__ float g_bkv[KVROW];
__device__ float g_sintab[SEQ * 64];
__device__ float g_costab[SEQ * 64];

// ---------------------------------------------------------------------------
// helpers
// ---------------------------------------------------------------------------
__device__ __forceinline__ unsigned f2tf32(float x) {
    unsigned r;
    asm("cvt.rna.tf32.f32 %0, %1;" : "=r"(r) : "f"(x));
    return r;
}
__device__ __forceinline__ float rna_tf32f(float x) { return __uint_as_float(f2tf32(x)); }

__device__ __forceinline__ uint32_t smem_u32(const void* p) {
    uint32_t a;
    asm("{ .reg .u64 t; cvta.to.shared.u64 t, %1; cvt.u32.u64 %0, t; }" : "=r"(a) : "l"(p));
    return a;
}
__device__ __forceinline__ void cp16(uint32_t saddr, const void* g) {
    asm volatile("cp.async.cg.shared.global [%0], [%1], 16;" :: "r"(saddr), "l"(g));
}
__device__ __forceinline__ void cp_commit() { asm volatile("cp.async.commit_group;" ::: "memory"); }

__device__ __forceinline__ void ldsm_x4(uint32_t a[4], uint32_t addr) {
    asm volatile("ldmatrix.sync.aligned.m8n8.x4.shared.b16 {%0,%1,%2,%3}, [%4];"
                 : "=r"(a[0]), "=r"(a[1]), "=r"(a[2]), "=r"(a[3]) : "r"(addr));
}

__device__ __forceinline__ void mma_tf32(float c[4], const uint32_t a[4], const uint32_t b[2]) {
    asm volatile(
        "mma.sync.aligned.m16n8k8.row.col.f32.tf32.tf32.f32 "
        "{%0,%1,%2,%3}, {%4,%5,%6,%7}, {%8,%9}, {%0,%1,%2,%3};"
        : "+f"(c[0]), "+f"(c[1]), "+f"(c[2]), "+f"(c[3])
        : "r"(a[0]), "r"(a[1]), "r"(a[2]), "r"(a[3]), "r"(b[0]), "r"(b[1]));
}

// ---------------------------------------------------------------------------
// Pre-pass kernels
// ---------------------------------------------------------------------------
__global__ void rope_table_kernel(float* __restrict__ sintab, float* __restrict__ costab) {
    const int s = blockIdx.x;
    const int i = threadIdx.x;   // 0..63
    float inv_freq = expf((float)i * (-LN10000 / 64.0f));
    float sn, cs;
    sincosf((float)s * inv_freq, &sn, &cs);
    sintab[s * 64 + i] = sn;
    costab[s * 64 + i] = cs;
}

__global__ void round_x_kernel(const float* __restrict__ x, float* __restrict__ xr, int n4) {
    int i = blockIdx.x * blockDim.x + threadIdx.x;
    if (i < n4) {
        float4 v = reinterpret_cast<const float4*>(x)[i];
        v.x = rna_tf32f(v.x); v.y = rna_tf32f(v.y);
        v.z = rna_tf32f(v.z); v.w = rna_tf32f(v.w);
        reinterpret_cast<float4*>(xr)[i] = v;
    }
}

__global__ void transpose_round_kernel(const float* __restrict__ W, float* __restrict__ WT,
                                       int K, int N) {
    __shared__ float t[32][33];
    int n0 = blockIdx.x * 32, k0 = blockIdx.y * 32;
    int tx = threadIdx.x, ty = threadIdx.y;
    #pragma unroll
    for (int j = 0; j < 32; j += 8)
        t[ty + j][tx] = W[(size_t)(k0 + ty + j) * N + n0 + tx];
    __syncthreads();
    #pragma unroll
    for (int j = 0; j < 32; j += 8)
        WT[(size_t)(n0 + ty + j) * K + k0 + tx] = rna_tf32f(t[tx][ty + j]);
}

__global__ void concat_bias_kernel(const float* __restrict__ bk, const float* __restrict__ bv,
                                   float* __restrict__ bkv) {
    int i = blockIdx.x * blockDim.x + threadIdx.x;
    if (i < KVROW) bkv[i] = (i < KVD) ? bk[i] : bv[i - KVD];
}

// ---------------------------------------------------------------------------
// TF32 mma.sync GEMM: C[M,N] = A[M,K] @ BT[N,K]^T + bias[N]
// CTA 128x128, BK=32, 3-stage cp.async, paired-x4 ldmatrix fragments.
// ---------------------------------------------------------------------------
#define BK 32
#define STAGE_BYTES 32768
#define GSM_B_OFF 16384
#define GEMM_SMEM_BYTES (3 * STAGE_BYTES)   // 98304

__device__ __forceinline__ uint32_t swz(int r, int chunk) {
    return (uint32_t)(r * 128 + ((chunk ^ (r & 7)) << 4));
}

__device__ __forceinline__ void gemm_load_stage(const float* __restrict__ A,
                                                const float* __restrict__ BT,
                                                int K, int m0, int n0, int kt,
                                                uint32_t sstage, int tid) {
    const int kbase = kt * BK;
    #pragma unroll
    for (int j = 0; j < 4; j++) {
        int i = tid + j * 256;
        int r = i >> 3, cc = i & 7;
        cp16(sstage + swz(r, cc), A + (size_t)(m0 + r) * K + kbase + cc * 4);
    }
    #pragma unroll
    for (int j = 0; j < 4; j++) {
        int i = tid + j * 256;
        int r = i >> 3, cc = i & 7;
        cp16(sstage + GSM_B_OFF + swz(r, cc), BT + (size_t)(n0 + r) * K + kbase + cc * 4);
    }
}

__global__ __launch_bounds__(256, 2)
void tf32_gemm_pipe(const float* __restrict__ A, const float* __restrict__ BT,
                    const float* __restrict__ bias, float* __restrict__ C,
                    int M, int N, int K, int roundC) {
    extern __shared__ char smem[];
    const uint32_t sbase = smem_u32(smem);
    const int tid = threadIdx.x;
    const int lane = tid & 31;
    const int wid = tid >> 5;
    const int warpRow = (wid >> 2) * 64;
    const int warpCol = (wid & 3) * 32;
    const int m0 = blockIdx.y * 128;
    const int n0 = blockIdx.x * 128;

    float acc[4][4][4];
    #pragma unroll
    for (int i = 0; i < 4; i++)
        #pragma unroll
        for (int j = 0; j < 4; j++)
            #pragma unroll
            for (int r = 0; r < 4; r++) acc[i][j][r] = 0.0f;

    const int NT = K / BK;

    const int a_sub = lane >> 3;
    const int a_row_in = (lane & 7) + (a_sub & 1) * 8;
    const int a_chunk_add = a_sub >> 1;
    const int b_sub = (lane >> 3) & 1;
    const int b_pair_row = ((lane >> 4) & 1) * 8 + (lane & 7);

    gemm_load_stage(A, BT, K, m0, n0, 0, sbase, tid);
    cp_commit();
    gemm_load_stage(A, BT, K, m0, n0, 1, sbase + STAGE_BYTES, tid);
    cp_commit();

    for (int kt = 0; kt < NT; kt++) {
        if (kt + 2 < NT) {
            asm volatile("cp.async.wait_group 1;" ::: "memory");
        } else {
            asm volatile("cp.async.wait_group 0;" ::: "memory");
        }
        __syncthreads();
        if (kt + 2 < NT) {
            gemm_load_stage(A, BT, K, m0, n0, kt + 2,
                            sbase + ((kt + 2) % 3) * STAGE_BYTES, tid);
            cp_commit();
        }

        const uint32_t sA = sbase + (kt % 3) * STAGE_BYTES;
        const uint32_t sB = sA + GSM_B_OFF;

        #pragma unroll
        for (int ks = 0; ks < 4; ks++) {
            uint32_t af[4][4];
            uint32_t bf[2][4];
            #pragma unroll
            for (int it = 0; it < 4; it++) {
                int r = warpRow + it * 16 + a_row_in;
                ldsm_x4(af[it], sA + swz(r, ks * 2 + a_chunk_add));
            }
            #pragma unroll
            for (int jp = 0; jp < 2; jp++) {
                int r = warpCol + jp * 16 + b_pair_row;
                ldsm_x4(bf[jp], sB + swz(r, ks * 2 + b_sub));
            }
            #pragma unroll
            for (int it = 0; it < 4; it++) {
                #pragma unroll
                for (int jp = 0; jp < 2; jp++) {
                    mma_tf32(acc[it][jp * 2 + 0], af[it], &bf[jp][0]);
                    mma_tf32(acc[it][jp * 2 + 1], af[it], &bf[jp][2]);
                }
            }
        }
    }

    const int lr = lane >> 2;
    const int lc = lane & 3;
    #pragma unroll
    for (int it = 0; it < 4; it++) {
        #pragma unroll
        for (int jt = 0; jt < 4; jt++) {
            int row = m0 + warpRow + it * 16 + lr;
            int col = n0 + warpCol + jt * 8 + 2 * lc;
            float b0 = bias[col];
            float b1 = bias[col + 1];
            float2 v0 = make_float2(acc[it][jt][0] + b0, acc[it][jt][1] + b1);
            float2 v1 = make_float2(acc[it][jt][2] + b0, acc[it][jt][3] + b1);
            if (roundC) {
                v0.x = rna_tf32f(v0.x); v0.y = rna_tf32f(v0.y);
                v1.x = rna_tf32f(v1.x); v1.y = rna_tf32f(v1.y);
            }
            *reinterpret_cast<float2*>(&C[(size_t)row * N + col]) = v0;
            *reinterpret_cast<float2*>(&C[(size_t)(row + 8) * N + col]) = v1;
        }
    }
}

// ---------------------------------------------------------------------------
// fast fused RMSNorm + RoPE: one warp per 128-vector, table-based trig.
// ---------------------------------------------------------------------------
__global__ __launch_bounds__(256)
void rmsnorm_rope_fast(float* __restrict__ buf, const float* __restrict__ scale,
                       const float* __restrict__ sintab, const float* __restrict__ costab,
                       int heads_per_row, int rowstride, float post_scale) {
    const int vec = blockIdx.x * 8 + (threadIdx.x >> 5);
    const int lane = threadIdx.x & 31;
    const int row = vec / heads_per_row;
    const int head = vec % heads_per_row;
    float* ptr = buf + (size_t)row * rowstride + head * HEADD + lane * 4;
    const int s = row & (SEQ - 1);

    float4 v = *reinterpret_cast<const float4*>(ptr);
    float sq = fmaf(v.x, v.x, fmaf(v.y, v.y, fmaf(v.z, v.z, v.w * v.w)));
    #pragma unroll
    for (int o = 16; o > 0; o >>= 1) sq += __shfl_xor_sync(0xffffffffu, sq, o);
    const float r = rsqrtf(sq * (1.0f / 128.0f) + 1e-6f);

    const float4 sc = *reinterpret_cast<const float4*>(scale + lane * 4);
    const float a0 = v.x * r * sc.x;
    const float a1 = v.y * r * sc.y;
    const float a2 = v.z * r * sc.z;
    const float a3 = v.w * r * sc.w;

    const float2 sn = *reinterpret_cast<const float2*>(sintab + s * 64 + lane * 2);
    const float2 cs = *reinterpret_cast<const float2*>(costab + s * 64 + lane * 2);

    float4 o4;
    o4.x = rna_tf32f(fmaf(a0, cs.x, -a1 * sn.x) * post_scale);
    o4.y = rna_tf32f(fmaf(a0, sn.x,  a1 * cs.x) * post_scale);
    o4.z = rna_tf32f(fmaf(a2, cs.y, -a3 * sn.y) * post_scale);
    o4.w = rna_tf32f(fmaf(a2, sn.y,  a3 * cs.y) * post_scale);
    *reinterpret_cast<float4*>(ptr) = o4;
}

// ---------------------------------------------------------------------------
// Tensor-core causal attention; K paired-x4 fragments, P via ldmatrix.
// ---------------------------------------------------------------------------
#define ATT_SC_STRIDE 516
#define ATT_Q_OFF  (64 * ATT_SC_STRIDE * 4)            // 132096
#define ATT_KV_OFF (ATT_Q_OFF + 32768)                 // 164864
#define ATT_SMEM_BYTES (ATT_KV_OFF + 65536)            // 230400

__device__ __forceinline__ uint32_t qswz(int r, int c) {
    return (uint32_t)(r * 512 + ((((c ^ r) & 7) | (c & 24)) << 4));
}

__global__ __launch_bounds__(256, 1)
void attention_tc_kernel(const float* __restrict__ Q, const float* __restrict__ KV,
                         float* __restrict__ O, int bh_off) {
    extern __shared__ char smemraw[];
    float* scores = reinterpret_cast<float*>(smemraw);
    float* Vs = reinterpret_cast<float*>(smemraw + ATT_KV_OFF);
    const uint32_t sbase = smem_u32(smemraw);
    const uint32_t sQ = sbase + ATT_Q_OFF;
    const uint32_t sKV = sbase + ATT_KV_OFF;

    const int tid = threadIdx.x;
    const int lane = tid & 31;
    const int wid = tid >> 5;
    const int qt = blockIdx.x;
    const int bh = blockIdx.y + bh_off;
    const int b = bh / NHEADS;
    const int h = bh % NHEADS;
    const int g = h / PPG;

    const float* Qbase = Q + (size_t)b * SEQ * DMODEL + (size_t)h * HEADD;
    const float* Kbase = KV + (size_t)b * SEQ * KVROW + (size_t)g * HEADD;
    const float* Vbase = KV + (size_t)b * SEQ * KVROW + KVD + (size_t)g * HEADD;

    #pragma unroll
    for (int j = 0; j < 8; j++) {
        int idx = tid + j * 256;
        int r = idx >> 5, c = idx & 31;
        cp16(sQ + qswz(r, c), Qbase + (size_t)(qt * 64 + r) * DMODEL + c * 4);
    }
    #pragma unroll
    for (int j = 0; j < 8; j++) {
        int idx = tid + j * 256;
        int r = idx >> 5, c = idx & 31;
        cp16(sKV + qswz(r, c), Kbase + (size_t)r * KVROW + c * 4);
    }
    cp_commit();
    asm volatile("cp.async.wait_group 0;" ::: "memory");
    __syncthreads();

    const int a_sub = lane >> 3;
    const int a_row_in = (lane & 7) + (a_sub & 1) * 8;
    const int a_chunk_add = a_sub >> 1;
    const int b_sub = (lane >> 3) & 1;
    const int b_pair_row = ((lane >> 4) & 1) * 8 + (lane & 7);
    const int lr = lane >> 2;
    const int lc = lane & 3;
    const int warpRowS = (wid & 3) * 16;
    const int warpColS = (wid >> 2) * 32;

    // ---------------- phase 1: scores = Q @ K^T ----------------
    for (int kt = 0; kt <= qt; kt++) {
        const int buf = kt & 1;
        if (kt < qt) {
            #pragma unroll
            for (int j = 0; j < 8; j++) {
                int idx = tid + j * 256;
                int r = idx >> 5, c = idx & 31;
                cp16(sKV + (1 - buf) * 32768 + qswz(r, c),
                     Kbase + (size_t)((kt + 1) * 64 + r) * KVROW + c * 4);
            }
            cp_commit();
        }
        const uint32_t sK = sKV + buf * 32768;

        float acc[4][4];
        #pragma unroll
        for (int i = 0; i < 4; i++)
            #pragma unroll
            for (int j = 0; j < 4; j++) acc[i][j] = 0.0f;

        #pragma unroll
        for (int ks = 0; ks < 16; ks++) {
            uint32_t af[4];
            ldsm_x4(af, sQ + qswz(warpRowS + a_row_in, ks * 2 + a_chunk_add));
            #pragma unroll
            for (int jp = 0; jp < 2; jp++) {
                uint32_t bf[4];
                ldsm_x4(bf, sK + qswz(warpColS + jp * 16 + b_pair_row, ks * 2 + b_sub));
                mma_tf32(acc[jp * 2 + 0], af, &bf[0]);
                mma_tf32(acc[jp * 2 + 1], af, &bf[2]);
            }
        }

        #pragma unroll
        for (int jt = 0; jt < 4; jt++) {
            int r0 = warpRowS + lr;
            int r1 = r0 + 8;
            int c0 = kt * 64 + warpColS + jt * 8 + 2 * lc;
            int g0 = qt * 64 + r0;
            int g1 = qt * 64 + r1;
            float2 v0, v1;
            v0.x = (c0 <= g0) ? acc[jt][0] * INV_SQRT_HD : -1e30f;
            v0.y = (c0 + 1 <= g0) ? acc[jt][1] * INV_SQRT_HD : -1e30f;
            v1.x = (c0 <= g1) ? acc[jt][2] * INV_SQRT_HD : -1e30f;
            v1.y = (c0 + 1 <= g1) ? acc[jt][3] * INV_SQRT_HD : -1e30f;
            *reinterpret_cast<float2*>(&scores[r0 * ATT_SC_STRIDE + c0]) = v0;
            *reinterpret_cast<float2*>(&scores[r1 * ATT_SC_STRIDE + c0]) = v1;
        }
        if (kt < qt) asm volatile("cp.async.wait_group 0;" ::: "memory");
        __syncthreads();
    }

    // prefetch V tile 0
    #pragma unroll
    for (int j = 0; j < 8; j++) {
        int idx = tid + j * 256;
        int r = idx >> 5, c = idx & 31;
        cp16(sKV + r * 528 + c * 16, Vbase + (size_t)r * KVROW + c * 4);
    }
    cp_commit();

    // ---------------- phase 2: softmax ----------------
    {
        const int ncols = (qt + 1) * 64;
        for (int r = wid; r < 64; r += 8) {
            float* row = &scores[r * ATT_SC_STRIDE];
            float m = -1e30f;
            for (int c = lane; c < ncols; c += 32) m = fmaxf(m, row[c]);
            #pragma unroll
            for (int o = 16; o > 0; o >>= 1) m = fmaxf(m, __shfl_xor_sync(0xffffffffu, m, o));
            float sum = 0.0f;
            for (int c = lane; c < ncols; c += 32) {
                float e = __expf(row[c] - m);
                row[c] = e;
                sum += e;
            }
            #pragma unroll
            for (int o = 16; o > 0; o >>= 1) sum += __shfl_xor_sync(0xffffffffu, sum, o);
            float inv = 1.0f / sum;
            for (int c = lane; c < ncols; c += 32) row[c] = rna_tf32f(row[c] * inv);
        }
    }
    __syncthreads();

    // ---------------- phase 3: O = P @ V ----------------
    const int warpRowO = (wid & 3) * 16;
    const int warpColO = (wid >> 2) * 64;
    float oacc[8][4];
    #pragma unroll
    for (int i = 0; i < 8; i++)
        #pragma unroll
        for (int j = 0; j < 4; j++) oacc[i][j] = 0.0f;

    for (int kt = 0; kt <= qt; kt++) {
        asm volatile("cp.async.wait_group 0;" ::: "memory");
        __syncthreads();

        #pragma unroll
        for (int ks = 0; ks < 8; ks++) {
            const int kabs = kt * 64 + ks * 8;
            uint32_t af[4];
            ldsm_x4(af, sbase + (uint32_t)(((warpRowO + a_row_in) * ATT_SC_STRIDE + kabs) * 4)
                        + a_chunk_add * 16);
            #pragma unroll
            for (int jt = 0; jt < 8; jt++) {
                const int ncol = warpColO + jt * 8 + lr;
                uint32_t bf[2];
                bf[0] = __float_as_uint(Vs[(ks * 8 + lc) * 132 + ncol]);
                bf[1] = __float_as_uint(Vs[(ks * 8 + lc + 4) * 132 + ncol]);
                mma_tf32(oacc[jt], af, bf);
            }
        }
        __syncthreads();
        if (kt < qt) {
            #pragma unroll
            for (int j = 0; j < 8; j++) {
                int idx = tid + j * 256;
                int r = idx >> 5, c = idx & 31;
                cp16(sKV + r * 528 + c * 16,
                     Vbase + (size_t)((kt + 1) * 64 + r) * KVROW + c * 4);
            }
            cp_commit();
        }
    }

    #pragma unroll
    for (int jt = 0; jt < 8; jt++) {
        int r0 = qt * 64 + warpRowO + lr;
        int col = h * HEADD + warpColO + jt * 8 + 2 * lc;
        float* d0 = &O[((size_t)b * SEQ + r0) * DMODEL + col];
        float* d1 = &O[((size_t)b * SEQ + r0 + 8) * DMODEL + col];
        float2 v0 = make_float2(rna_tf32f(oacc[jt][0]), rna_tf32f(oacc[jt][1]));
        float2 v1 = make_float2(rna_tf32f(oacc[jt][2]), rna_tf32f(oacc[jt][3]));
        *reinterpret_cast<float2*>(d0) = v0;
        *reinterpret_cast<float2*>(d1) = v1;
    }
}

// ---------------------------------------------------------------------------
// Launch: R14 graph + attention/Wo batch-half split across the two streams
// ---------------------------------------------------------------------------
extern "C" void kernel_launch(void* const* d_in, const int* in_sizes, int n_in,
                              void* d_out, int out_size) {
    const float* x  = (const float*)d_in[0];
    const float* Wq = (const float*)d_in[1];
    const float* bq = (const float*)d_in[2];
    const float* Wk = (const float*)d_in[3];
    const float* bk = (const float*)d_in[4];
    const float* Wv = (const float*)d_in[5];
    const float* bv = (const float*)d_in[6];
    const float* Wo = (const float*)d_in[7];
    const float* bo = (const float*)d_in[8];
    const float* qns = (const float*)d_in[9];
    const float* kns = (const float*)d_in[10];
    float* out = (float*)d_out;

    float *qb, *kvb, *ab, *xr, *wqt, *wkvt, *wot, *bkv, *stab, *ctab;
    cudaGetSymbolAddress((void**)&qb, g_q);
    cudaGetSymbolAddress((void**)&kvb, g_kv);
    cudaGetSymbolAddress((void**)&ab, g_attn);
    cudaGetSymbolAddress((void**)&xr, g_xr);
    cudaGetSymbolAddress((void**)&wqt, g_wqt);
    cudaGetSymbolAddress((void**)&wkvt, g_wkvt);
    cudaGetSymbolAddress((void**)&wot, g_wot);
    cudaGetSymbolAddress((void**)&bkv, g_bkv);
    cudaGetSymbolAddress((void**)&stab, g_sintab);
    cudaGetSymbolAddress((void**)&ctab, g_costab);

    cudaFuncSetAttribute(tf32_gemm_pipe, cudaFuncAttributeMaxDynamicSharedMemorySize,
                         GEMM_SMEM_BYTES);
    cudaFuncSetAttribute(attention_tc_kernel, cudaFuncAttributeMaxDynamicSharedMemorySize,
                         ATT_SMEM_BYTES);

    cudaStream_t skv;
    cudaEvent_t ev_root, ev_x, ev_q, ev_kv, ev_w, ev_fin;
    cudaStreamCreateWithFlags(&skv, cudaStreamNonBlocking);
    cudaEventCreateWithFlags(&ev_root, cudaEventDisableTiming);
    cudaEventCreateWithFlags(&ev_x, cudaEventDisableTiming);
    cudaEventCreateWithFlags(&ev_q, cudaEventDisableTiming);
    cudaEventCreateWithFlags(&ev_kv, cudaEventDisableTiming);
    cudaEventCreateWithFlags(&ev_w, cudaEventDisableTiming);
    cudaEventCreateWithFlags(&ev_fin, cudaEventDisableTiming);

    dim3 tb(32, 8);

    // fork point
    cudaEventRecord(ev_root, 0);
    cudaStreamWaitEvent(skv, ev_root, 0);

    // stream0: tables, x rounding, Wq transpose, Q GEMM, Q rmsnorm
    rope_table_kernel<<<SEQ, 64>>>(stab, ctab);
    {
        int n4 = MROWS * DMODEL / 4;
        round_x_kernel<<<(n4 + 255) / 256, 256>>>(x, xr, n4);
    }
    cudaEventRecord(ev_x, 0);    // xr + tables ready

    transpose_round_kernel<<<dim3(DMODEL / 32, DMODEL / 32), tb>>>(Wq, wqt, DMODEL, DMODEL);
    tf32_gemm_pipe<<<dim3(DMODEL / 128, MROWS / 128), 256, GEMM_SMEM_BYTES>>>(
        xr, wqt, bq, qb, MROWS, DMODEL, DMODEL, 0);
    rmsnorm_rope_fast<<<MROWS * NHEADS / 8, 256>>>(qb, qns, stab, ctab,
                                                   NHEADS, DMODEL, INV_SQRT_HD);
    cudaEventRecord(ev_q, 0);

    // skv: Wk/Wv/Wo transposes, concat bias, KV GEMM, K rmsnorm
    transpose_round_kernel<<<dim3(KVD / 32, DMODEL / 32), tb, 0, skv>>>(Wk, wkvt, DMODEL, KVD);
    transpose_round_kernel<<<dim3(KVD / 32, DMODEL / 32), tb, 0, skv>>>(
        Wv, wkvt + (size_t)KVD * DMODEL, DMODEL, KVD);
    transpose_round_kernel<<<dim3(DMODEL / 32, DMODEL / 32), tb, 0, skv>>>(Wo, wot, DMODEL, DMODEL);
    cudaEventRecord(ev_w, skv);
    concat_bias_kernel<<<4, 256, 0, skv>>>(bk, bv, bkv);
    cudaStreamWaitEvent(skv, ev_x, 0);
    tf32_gemm_pipe<<<dim3(KVROW / 128, MROWS / 128), 256, GEMM_SMEM_BYTES, skv>>>(
        xr, wkvt, bkv, kvb, MROWS, KVROW, DMODEL, 1);
    rmsnorm_rope_fast<<<MROWS * NGROUPS / 8, 256, 0, skv>>>(kvb, kns, stab, ctab,
                                                            NGROUPS, KVROW, 1.0f);
    cudaEventRecord(ev_kv, skv);

    // stream0: attn half 1 (b 0..7), then Wo half 1
    cudaStreamWaitEvent(0, ev_kv, 0);
    attention_tc_kernel<<<dim3(SEQ / 64, BATCH * NHEADS / 2), 256, ATT_SMEM_BYTES>>>(
        qb, kvb, ab, 0);
    cudaStreamWaitEvent(0, ev_w, 0);
    tf32_gemm_pipe<<<dim3(DMODEL / 128, (MROWS / 2) / 128), 256, GEMM_SMEM_BYTES>>>(
        ab, wot, bo, out, MROWS / 2, DMODEL, DMODEL, 0);

    // skv: attn half 2 (b 8..15), then Wo half 2
    cudaStreamWaitEvent(skv, ev_q, 0);
    attention_tc_kernel<<<dim3(SEQ / 64, BATCH * NHEADS / 2), 256, ATT_SMEM_BYTES, skv>>>(
        qb, kvb, ab, BATCH * NHEADS / 2);
    tf32_gemm_pipe<<<dim3(DMODEL / 128, (MROWS / 2) / 128), 256, GEMM_SMEM_BYTES, skv>>>(
        ab + (size_t)(MROWS / 2) * DMODEL, wot, bo, out + (size_t)(MROWS / 2) * DMODEL,
        MROWS / 2, DMODEL, DMODEL, 0);
    cudaEventRecord(ev_fin, skv);

    // join so the captured graph's stream-0 endpoint depends on skv's work
    cudaStreamWaitEvent(0, ev_fin, 0);
}